// round 3
// baseline (speedup 1.0000x reference)
#include <cuda_runtime.h>
#include <math.h>

// Problem dims (B fixed by problem; C, N, NSE derived at launch from sizes)
#define BATCH 256
#define C_MAX 32768
#define N_MAX 8192
#define NSE_MAX (1 << 20)

// ---- scratch (__device__ globals: alloc-free per harness rules) ----
__device__ float g_expllT[(size_t)C_MAX * BATCH];   // exp(child_ll) transposed [C, B]  (32 MB)
__device__ float g_outT[(size_t)N_MAX * BATCH];     // result transposed [N, B]          (8 MB)
__device__ float g_expw[NSE_MAX];                   // exp(log_w - m)                    (4 MB)
__device__ float g_partmax[256];
__device__ float g_max;

// ---------------------------------------------------------------------------
// 1a. partial max over log_w
__global__ void max_stage1(const float* __restrict__ lw, int nse) {
    float m = -INFINITY;
    for (int i = blockIdx.x * blockDim.x + threadIdx.x; i < nse;
         i += gridDim.x * blockDim.x)
        m = fmaxf(m, lw[i]);
    __shared__ float s[256];
    s[threadIdx.x] = m;
    __syncthreads();
    for (int o = 128; o > 0; o >>= 1) {
        if (threadIdx.x < o) s[threadIdx.x] = fmaxf(s[threadIdx.x], s[threadIdx.x + o]);
        __syncthreads();
    }
    if (threadIdx.x == 0) g_partmax[blockIdx.x] = s[0];
}

// 1b. final max
__global__ void max_stage2() {
    __shared__ float s[256];
    s[threadIdx.x] = g_partmax[threadIdx.x];
    __syncthreads();
    for (int o = 128; o > 0; o >>= 1) {
        if (threadIdx.x < o) s[threadIdx.x] = fmaxf(s[threadIdx.x], s[threadIdx.x + o]);
        __syncthreads();
    }
    if (threadIdx.x == 0) g_max = s[0];
}

// ---------------------------------------------------------------------------
// 2. expw[e] = exp(log_w[e] - m)
__global__ void expw_kernel(const float* __restrict__ lw, int nse) {
    float m = g_max;
    for (int i = blockIdx.x * blockDim.x + threadIdx.x; i < nse;
         i += gridDim.x * blockDim.x)
        g_expw[i] = __expf(lw[i] - m);
}

// ---------------------------------------------------------------------------
// 3. exp + transpose: child_ll [B, C] -> g_expllT [C, B]
__global__ void transpose_exp(const float* __restrict__ cll, int Cdim) {
    __shared__ float t[32][33];
    int c0 = blockIdx.x * 32;
    int b0 = blockIdx.y * 32;
    #pragma unroll
    for (int i = threadIdx.y; i < 32; i += 8)
        t[i][threadIdx.x] = cll[(size_t)(b0 + i) * Cdim + (c0 + threadIdx.x)];
    __syncthreads();
    #pragma unroll
    for (int i = threadIdx.y; i < 32; i += 8)
        g_expllT[(size_t)(c0 + i) * BATCH + (b0 + threadIdx.x)] =
            __expf(t[threadIdx.x][i]);
}

// ---------------------------------------------------------------------------
// 4. main: one block per sum node, one thread per batch element.
//    outT[n, b] = log(sum_e expw[e]*expllT[col[e], b]) - log(sum_e expw[e])
__device__ __forceinline__ int lbound(const int* __restrict__ a, int n, int key) {
    int lo = 0, hi = n;
    while (lo < hi) {
        int mid = (lo + hi) >> 1;
        if (a[mid] < key) lo = mid + 1; else hi = mid;
    }
    return lo;
}

__global__ __launch_bounds__(256) void main_kernel(
    const int* __restrict__ rows, const int* __restrict__ cols, int nse) {
    int n = blockIdx.x;
    int tid = threadIdx.x;

    // edge range for this node (rows is sorted, every node has >=1 edge)
    int lo = lbound(rows, nse, n);
    int hi = lbound(rows, nse, n + 1);

    __shared__ float s_w[256];
    __shared__ int   s_c[256];

    float acc  = 0.f;   // sum_e w*x  (per batch lane)
    float accz = 0.f;   // sum_e w    (uniform; recomputed per lane, cheap)

    for (int base = lo; base < hi; base += 256) {
        int cnt = min(256, hi - base);
        __syncthreads();
        if (tid < cnt) {
            s_w[tid] = g_expw[base + tid];
            s_c[tid] = cols[base + tid];
        }
        __syncthreads();
        int j = 0;
        for (; j + 4 <= cnt; j += 4) {
            float w0 = s_w[j],     w1 = s_w[j + 1], w2 = s_w[j + 2], w3 = s_w[j + 3];
            int   c0 = s_c[j],     c1 = s_c[j + 1], c2 = s_c[j + 2], c3 = s_c[j + 3];
            float x0 = __ldg(&g_expllT[c0 * BATCH + tid]);
            float x1 = __ldg(&g_expllT[c1 * BATCH + tid]);
            float x2 = __ldg(&g_expllT[c2 * BATCH + tid]);
            float x3 = __ldg(&g_expllT[c3 * BATCH + tid]);
            acc = fmaf(w0, x0, acc);
            acc = fmaf(w1, x1, acc);
            acc = fmaf(w2, x2, acc);
            acc = fmaf(w3, x3, acc);
            accz += (w0 + w1) + (w2 + w3);
        }
        for (; j < cnt; j++) {
            float w = s_w[j];
            acc = fmaf(w, __ldg(&g_expllT[s_c[j] * BATCH + tid]), acc);
            accz += w;
        }
    }
    g_outT[(size_t)n * BATCH + tid] = __logf(acc) - __logf(accz);
}

// ---------------------------------------------------------------------------
// 5. final transpose: g_outT [N, B] -> out [B, N]
__global__ void transpose_out(float* __restrict__ out, int Ndim) {
    __shared__ float t[32][33];
    int n0 = blockIdx.x * 32;
    int b0 = blockIdx.y * 32;
    #pragma unroll
    for (int i = threadIdx.y; i < 32; i += 8)
        t[i][threadIdx.x] = g_outT[(size_t)(n0 + i) * BATCH + (b0 + threadIdx.x)];
    __syncthreads();
    #pragma unroll
    for (int i = threadIdx.y; i < 32; i += 8)
        out[(size_t)(b0 + i) * Ndim + (n0 + threadIdx.x)] = t[threadIdx.x][i];
}

// ---------------------------------------------------------------------------
extern "C" void kernel_launch(void* const* d_in, const int* in_sizes, int n_in,
                              void* d_out, int out_size) {
    const float* child_ll = (const float*)d_in[0];   // [B, C]
    const float* log_w    = (const float*)d_in[1];   // [NSE]
    const int*   rows     = (const int*)d_in[2];     // [NSE] sorted
    const int*   cols     = (const int*)d_in[3];     // [NSE]
    float*       out      = (float*)d_out;           // [B, N]

    int NSE  = in_sizes[1];
    int Cdim = in_sizes[0] / BATCH;
    int Ndim = out_size / BATCH;

    // 1. global max of log_w (deterministic two-stage)
    max_stage1<<<256, 256>>>(log_w, NSE);
    max_stage2<<<1, 256>>>();

    // 2. exp(log_w - m)
    expw_kernel<<<(NSE + 1023) / 1024, 256>>>(log_w, NSE);

    // 3. exp + transpose child_ll -> [C, B]
    transpose_exp<<<dim3(Cdim / 32, BATCH / 32), dim3(32, 8)>>>(child_ll, Cdim);

    // 4. main sparse row reduction: one block per node
    main_kernel<<<Ndim, 256>>>(rows, cols, NSE);

    // 5. transpose result -> [B, N]
    transpose_out<<<dim3(Ndim / 32, BATCH / 32), dim3(32, 8)>>>(out, Ndim);
}

// round 5
// speedup vs baseline: 2.3861x; 2.3861x over previous
#include <cuda_runtime.h>
#include <cuda_fp16.h>
#include <math.h>

#define BATCH 256
#define C_MAX 32768
#define N_MAX 8192
#define NSE_MAX (1 << 20)

// ---- scratch (__device__ globals: alloc-free per harness rules) ----
__device__ __half g_expllT[(size_t)C_MAX * BATCH];  // exp(child_ll) transposed [C, B], fp16 (16 MB)
__device__ float  g_outT[(size_t)N_MAX * BATCH];    // result transposed [N, B]            (8 MB)
__device__ float2 g_wc[NSE_MAX];                    // {exp(log_w - m), bits(col)}         (8 MB)
__device__ int    g_rowptr[N_MAX + 1];
__device__ float  g_partmax[256];
__device__ float  g_max;

// ---------------------------------------------------------------------------
// 1a/1b. global max of log_w (deterministic two-stage)
__global__ void max_stage1(const float* __restrict__ lw, int nse) {
    float m = -INFINITY;
    for (int i = blockIdx.x * blockDim.x + threadIdx.x; i < nse;
         i += gridDim.x * blockDim.x)
        m = fmaxf(m, lw[i]);
    __shared__ float s[256];
    s[threadIdx.x] = m;
    __syncthreads();
    for (int o = 128; o > 0; o >>= 1) {
        if (threadIdx.x < o) s[threadIdx.x] = fmaxf(s[threadIdx.x], s[threadIdx.x + o]);
        __syncthreads();
    }
    if (threadIdx.x == 0) g_partmax[blockIdx.x] = s[0];
}

__global__ void max_stage2() {
    __shared__ float s[256];
    s[threadIdx.x] = g_partmax[threadIdx.x];
    __syncthreads();
    for (int o = 128; o > 0; o >>= 1) {
        if (threadIdx.x < o) s[threadIdx.x] = fmaxf(s[threadIdx.x], s[threadIdx.x + o]);
        __syncthreads();
    }
    if (threadIdx.x == 0) g_max = s[0];
}

// ---------------------------------------------------------------------------
// 2. pack {expw, col} per edge; also build rowptr from sorted rows
__global__ void pack_wc_kernel(const float* __restrict__ lw,
                               const int* __restrict__ rows,
                               const int* __restrict__ cols,
                               int nse, int Ndim) {
    float m = g_max;
    int stride = gridDim.x * blockDim.x;
    for (int i = blockIdx.x * blockDim.x + threadIdx.x; i < nse; i += stride) {
        g_wc[i] = make_float2(__expf(lw[i] - m), __int_as_float(cols[i]));
        if (i == 0 || rows[i] != rows[i - 1]) g_rowptr[rows[i]] = i;
    }
    if (blockIdx.x == 0 && threadIdx.x == 0) g_rowptr[Ndim] = nse;
}

// ---------------------------------------------------------------------------
// 3. exp + transpose: child_ll [B, C] fp32 -> g_expllT [C, B] fp16
//    tile: 32 C x 64 B, block (32, 8)
__global__ __launch_bounds__(256) void transpose_exp(const float* __restrict__ cll, int Cdim) {
    __shared__ float s[32][65];
    int tx = threadIdx.x, ty = threadIdx.y;
    int c0 = blockIdx.x * 32;
    int b0 = blockIdx.y * 64;
    #pragma unroll
    for (int k = 0; k < 8; k++) {
        int bi = ty * 8 + k;
        s[tx][bi] = cll[(size_t)(b0 + bi) * Cdim + (c0 + tx)];
    }
    __syncthreads();
    #pragma unroll
    for (int k = 0; k < 4; k++) {
        int ci = ty + 8 * k;
        float e0 = __expf(s[ci][2 * tx]);
        float e1 = __expf(s[ci][2 * tx + 1]);
        *(__half2*)(g_expllT + (size_t)(c0 + ci) * BATCH + b0 + 2 * tx) =
            __floats2half2_rn(e0, e1);
    }
}

// ---------------------------------------------------------------------------
// 4. main: one WARP per sum node; lane owns 8 batch elements (one LDG.128/edge).
//    outT[n, b] = log(sum_e w_e * expllT[col_e, b]) - log(sum_e w_e)
__global__ __launch_bounds__(256) void main_kernel(int Ndim) {
    int n = blockIdx.x * 8 + (threadIdx.x >> 5);
    int lane = threadIdx.x & 31;
    if (n >= Ndim) return;

    int lo = g_rowptr[n];
    int hi = g_rowptr[n + 1];

    const __half* base = g_expllT + lane * 8;   // lane's 8 batch elems = 16B
    float a0 = 0.f, a1 = 0.f, a2 = 0.f, a3 = 0.f;
    float a4 = 0.f, a5 = 0.f, a6 = 0.f, a7 = 0.f;
    float accz = 0.f;

    #pragma unroll 4
    for (int e = lo; e < hi; e++) {
        float2 wc = g_wc[e];                    // broadcast LDG.64
        float w = wc.x;
        int   c = __float_as_int(wc.y);
        uint4 p = *(const uint4*)(base + (size_t)c * BATCH);  // gather LDG.128
        float2 f0 = __half22float2(*(const __half2*)&p.x);
        float2 f1 = __half22float2(*(const __half2*)&p.y);
        float2 f2 = __half22float2(*(const __half2*)&p.z);
        float2 f3 = __half22float2(*(const __half2*)&p.w);
        a0 = fmaf(w, f0.x, a0);  a1 = fmaf(w, f0.y, a1);
        a2 = fmaf(w, f1.x, a2);  a3 = fmaf(w, f1.y, a3);
        a4 = fmaf(w, f2.x, a4);  a5 = fmaf(w, f2.y, a5);
        a6 = fmaf(w, f3.x, a6);  a7 = fmaf(w, f3.y, a7);
        accz += w;
    }

    float z = __logf(accz);
    float* o = g_outT + (size_t)n * BATCH + lane * 8;
    float4 r0 = make_float4(__logf(a0) - z, __logf(a1) - z,
                            __logf(a2) - z, __logf(a3) - z);
    float4 r1 = make_float4(__logf(a4) - z, __logf(a5) - z,
                            __logf(a6) - z, __logf(a7) - z);
    *(float4*)o       = r0;
    *(float4*)(o + 4) = r1;
}

// ---------------------------------------------------------------------------
// 5. final transpose: g_outT [N, B] -> out [B, N]
__global__ void transpose_out(float* __restrict__ out, int Ndim) {
    __shared__ float t[32][33];
    int n0 = blockIdx.x * 32;
    int b0 = blockIdx.y * 32;
    #pragma unroll
    for (int i = threadIdx.y; i < 32; i += 8)
        t[i][threadIdx.x] = g_outT[(size_t)(n0 + i) * BATCH + (b0 + threadIdx.x)];
    __syncthreads();
    #pragma unroll
    for (int i = threadIdx.y; i < 32; i += 8)
        out[(size_t)(b0 + i) * Ndim + (n0 + threadIdx.x)] = t[threadIdx.x][i];
}

// ---------------------------------------------------------------------------
extern "C" void kernel_launch(void* const* d_in, const int* in_sizes, int n_in,
                              void* d_out, int out_size) {
    const float* child_ll = (const float*)d_in[0];   // [B, C]
    const float* log_w    = (const float*)d_in[1];   // [NSE]
    const int*   rows     = (const int*)d_in[2];     // [NSE] sorted
    const int*   cols     = (const int*)d_in[3];     // [NSE]
    float*       out      = (float*)d_out;           // [B, N]

    int NSE  = in_sizes[1];
    int Cdim = in_sizes[0] / BATCH;
    int Ndim = out_size / BATCH;

    // 1. global max of log_w
    max_stage1<<<256, 256>>>(log_w, NSE);
    max_stage2<<<1, 256>>>();

    // 2. pack {expw, col} + rowptr
    pack_wc_kernel<<<(NSE + 1023) / 1024, 256>>>(log_w, rows, cols, NSE, Ndim);

    // 3. exp + transpose child_ll -> fp16 [C, B]
    transpose_exp<<<dim3(Cdim / 32, BATCH / 64), dim3(32, 8)>>>(child_ll, Cdim);

    // 4. main sparse row reduction: one warp per node
    main_kernel<<<(Ndim + 7) / 8, 256>>>(Ndim);

    // 5. transpose result -> [B, N]
    transpose_out<<<dim3(Ndim / 32, BATCH / 32), dim3(32, 8)>>>(out, Ndim);
}

// round 8
// speedup vs baseline: 2.5000x; 1.0477x over previous
#include <cuda_runtime.h>
#include <cuda_fp16.h>
#include <math.h>

#define BATCH 256
#define C_MAX 32768
#define N_MAX 8192
#define NSE_MAX (1 << 20)

// ---- scratch (__device__ globals: alloc-free per harness rules) ----
__device__ __half g_expllT[(size_t)C_MAX * BATCH];  // exp(child_ll) transposed [C, B], fp16 (16 MB)
__device__ float  g_outT[(size_t)N_MAX * BATCH];    // result transposed [N, B]            (8 MB)
__device__ float2 g_wc[NSE_MAX];                    // {exp(log_w - m), bits(col)}         (8 MB)
__device__ int    g_rowptr[N_MAX + 1];
__device__ float  g_partmax[256];

// ---------------------------------------------------------------------------
// 1. partial max over log_w (256 blocks -> g_partmax)
__global__ void max_stage1(const float* __restrict__ lw, int nse) {
    float m = -INFINITY;
    for (int i = blockIdx.x * blockDim.x + threadIdx.x; i < nse;
         i += gridDim.x * blockDim.x)
        m = fmaxf(m, lw[i]);
    __shared__ float s[256];
    s[threadIdx.x] = m;
    __syncthreads();
    for (int o = 128; o > 0; o >>= 1) {
        if (threadIdx.x < o) s[threadIdx.x] = fmaxf(s[threadIdx.x], s[threadIdx.x + o]);
        __syncthreads();
    }
    if (threadIdx.x == 0) g_partmax[blockIdx.x] = s[0];
}

// ---------------------------------------------------------------------------
// 2. pack {expw, col} per edge + rowptr; final max folded in (each block
//    reduces the 256 L2-hot partials itself — saves a launch)
__global__ __launch_bounds__(256) void pack_wc_kernel(
    const float* __restrict__ lw, const int* __restrict__ rows,
    const int* __restrict__ cols, int nse, int Ndim) {
    __shared__ float s[256];
    s[threadIdx.x] = g_partmax[threadIdx.x];
    __syncthreads();
    for (int o = 128; o > 0; o >>= 1) {
        if (threadIdx.x < o) s[threadIdx.x] = fmaxf(s[threadIdx.x], s[threadIdx.x + o]);
        __syncthreads();
    }
    float m = s[0];

    int stride = gridDim.x * blockDim.x;
    for (int i = blockIdx.x * blockDim.x + threadIdx.x; i < nse; i += stride) {
        g_wc[i] = make_float2(__expf(lw[i] - m), __int_as_float(cols[i]));
        if (i == 0 || rows[i] != rows[i - 1]) g_rowptr[rows[i]] = i;
    }
    if (blockIdx.x == 0 && threadIdx.x == 0) g_rowptr[Ndim] = nse;
}

// ---------------------------------------------------------------------------
// 3. exp + transpose: child_ll [B, C] fp32 -> g_expllT [C, B] fp16
//    64C x 64B tile, float4 loads, half2 stores
__global__ __launch_bounds__(256) void transpose_exp(const float* __restrict__ cll, int Cdim) {
    __shared__ float s[64][65];
    int t = threadIdx.x;
    int c0 = blockIdx.x * 64;
    int b0 = blockIdx.y * 64;

    int bi0 = t >> 4;            // 0..15
    int cj  = (t & 15) * 4;      // 0..60
    #pragma unroll
    for (int k = 0; k < 4; k++) {
        int bi = bi0 + 16 * k;
        float4 v = *(const float4*)(cll + (size_t)(b0 + bi) * Cdim + c0 + cj);
        s[cj    ][bi] = __expf(v.x);
        s[cj + 1][bi] = __expf(v.y);
        s[cj + 2][bi] = __expf(v.z);
        s[cj + 3][bi] = __expf(v.w);
    }
    __syncthreads();

    int lane = t & 31, w = t >> 5;
    #pragma unroll
    for (int k = 0; k < 8; k++) {
        int ci = w + 8 * k;      // 0..63
        __half2 h = __floats2half2_rn(s[ci][2 * lane], s[ci][2 * lane + 1]);
        *(__half2*)(g_expllT + (size_t)(c0 + ci) * BATCH + b0 + 2 * lane) = h;
    }
}

// ---------------------------------------------------------------------------
// 4. main: one WARP per sum node; lane owns 8 batch elements (one LDG.128/edge).
//    outT[n, b] = log(sum_e w_e * expllT[col_e, b]) - log(sum_e w_e)
__global__ __launch_bounds__(256) void main_kernel(int Ndim) {
    int n = blockIdx.x * 8 + (threadIdx.x >> 5);
    int lane = threadIdx.x & 31;
    if (n >= Ndim) return;

    int lo = g_rowptr[n];
    int hi = g_rowptr[n + 1];

    const __half* base = g_expllT + lane * 8;   // lane's 8 batch elems = 16B
    float a0 = 0.f, a1 = 0.f, a2 = 0.f, a3 = 0.f;
    float a4 = 0.f, a5 = 0.f, a6 = 0.f, a7 = 0.f;
    float accz = 0.f;

    #pragma unroll 4
    for (int e = lo; e < hi; e++) {
        float2 wc = g_wc[e];                    // broadcast LDG.64
        float w = wc.x;
        int   c = __float_as_int(wc.y);
        uint4 p = *(const uint4*)(base + (size_t)c * BATCH);  // gather LDG.128
        float2 f0 = __half22float2(*(const __half2*)&p.x);
        float2 f1 = __half22float2(*(const __half2*)&p.y);
        float2 f2 = __half22float2(*(const __half2*)&p.z);
        float2 f3 = __half22float2(*(const __half2*)&p.w);
        a0 = fmaf(w, f0.x, a0);  a1 = fmaf(w, f0.y, a1);
        a2 = fmaf(w, f1.x, a2);  a3 = fmaf(w, f1.y, a3);
        a4 = fmaf(w, f2.x, a4);  a5 = fmaf(w, f2.y, a5);
        a6 = fmaf(w, f3.x, a6);  a7 = fmaf(w, f3.y, a7);
        accz += w;
    }

    float z = __logf(accz);
    float* o = g_outT + (size_t)n * BATCH + lane * 8;
    float4 r0 = make_float4(__logf(a0) - z, __logf(a1) - z,
                            __logf(a2) - z, __logf(a3) - z);
    float4 r1 = make_float4(__logf(a4) - z, __logf(a5) - z,
                            __logf(a6) - z, __logf(a7) - z);
    *(float4*)o       = r0;
    *(float4*)(o + 4) = r1;
}

// ---------------------------------------------------------------------------
// 5. final transpose: g_outT [N, B] -> out [B, N], float4 both phases
__global__ __launch_bounds__(256) void transpose_out(float* __restrict__ out, int Ndim) {
    __shared__ float s[64][65];
    int t = threadIdx.x;
    int n0 = blockIdx.x * 64;
    int b0 = blockIdx.y * 64;

    int ni0 = t >> 4;
    int bj  = (t & 15) * 4;
    #pragma unroll
    for (int k = 0; k < 4; k++) {
        int ni = ni0 + 16 * k;
        float4 v = *(const float4*)(g_outT + (size_t)(n0 + ni) * BATCH + b0 + bj);
        s[bj    ][ni] = v.x;
        s[bj + 1][ni] = v.y;
        s[bj + 2][ni] = v.z;
        s[bj + 3][ni] = v.w;
    }
    __syncthreads();

    int bi0 = t >> 4;
    int nj  = (t & 15) * 4;
    #pragma unroll
    for (int k = 0; k < 4; k++) {
        int bi = bi0 + 16 * k;
        float4 v = make_float4(s[bi][nj], s[bi][nj + 1],
                               s[bi][nj + 2], s[bi][nj + 3]);
        *(float4*)(out + (size_t)(b0 + bi) * Ndim + n0 + nj) = v;
    }
}

// ---------------------------------------------------------------------------
extern "C" void kernel_launch(void* const* d_in, const int* in_sizes, int n_in,
                              void* d_out, int out_size) {
    const float* child_ll = (const float*)d_in[0];   // [B, C]
    const float* log_w    = (const float*)d_in[1];   // [NSE]
    const int*   rows     = (const int*)d_in[2];     // [NSE] sorted
    const int*   cols     = (const int*)d_in[3];     // [NSE]
    float*       out      = (float*)d_out;           // [B, N]

    int NSE  = in_sizes[1];
    int Cdim = in_sizes[0] / BATCH;
    int Ndim = out_size / BATCH;

    // 1. partial max of log_w
    max_stage1<<<256, 256>>>(log_w, NSE);

    // 2. pack {expw, col} + rowptr (final max folded in)
    pack_wc_kernel<<<(NSE + 1023) / 1024, 256>>>(log_w, rows, cols, NSE, Ndim);

    // 3. exp + transpose child_ll -> fp16 [C, B]
    transpose_exp<<<dim3(Cdim / 64, BATCH / 64), 256>>>(child_ll, Cdim);

    // 4. main sparse row reduction: one warp per node
    main_kernel<<<(Ndim + 7) / 8, 256>>>(Ndim);

    // 5. transpose result -> [B, N]
    transpose_out<<<dim3(Ndim / 64, BATCH / 64), 256>>>(out, Ndim);
}